// round 3
// baseline (speedup 1.0000x reference)
#include <cuda_runtime.h>

#define T_STEPS 16
#define BATCH   32
#define HH      256
#define WW      256
#define TILE    32
#define E2W     36              // tile + 2*2 halo (layer-1 extent)
#define E1W     34              // tile + 2*1 halo (layer-2 extent)
#define E2A     (E2W*E2W)       // 1296
#define E1A     (E1W*E1W)       // 1156
#define NTH     320             // 10 warps
#define NWARPS  (NTH/32)
#define NS2     5               // ceil(1296/320) phase-A slots
#define NBLK    289             // 17x17 2x2-pixel blocks covering E1
#define NBW     (NWARPS*NS2)    // 50 ballot words (>= ceil(1296/32)=41)

__global__ void __launch_bounds__(NTH, 2) snn_kernel(
    const float* __restrict__ x,
    const float* __restrict__ w1,
    const float* __restrict__ w2,
    float* __restrict__ out)
{
    __shared__ unsigned           BITS[NBW];   // linear spike bits, one t
    __shared__ unsigned long long ROW[E2W];    // per-row 36-bit spike masks
    __shared__ float4             LUT[512];    // conv1 per 9-bit pattern
    __shared__ float              S2[4 * E1A]; // per-channel spike counts

    const int tid  = threadIdx.x;
    const int lane = tid & 31;
    const int wrp  = tid >> 5;
    const int tx0  = blockIdx.x * TILE;
    const int ty0  = blockIdx.y * TILE;
    const int b    = blockIdx.z;

    // ---- build conv1 LUT: bit (ky*3+kx) set => s1==1 at that tap --------
    {
        float w1r[36];
#pragma unroll
        for (int i = 0; i < 36; ++i) w1r[i] = __ldg(w1 + i);
        for (int p = tid; p < 512; p += NTH) {
            float a0 = 0.f, a1 = 0.f, a2 = 0.f, a3 = 0.f;
#pragma unroll
            for (int tap = 0; tap < 9; ++tap) {
                if (p & (1 << tap)) {
                    a0 += w1r[tap];
                    a1 += w1r[9  + tap];
                    a2 += w1r[18 + tap];
                    a3 += w1r[27 + tap];
                }
            }
            LUT[p] = make_float4(a0, a1, a2, a3);
        }
    }

    // ---- Phase-A slots: layer-1 state over E2 (tile + halo 2) ----------
    int   goff[NS2];   // offset into one time-slab of x, -1 if out of image
    float v1[NS2];
    float xc[NS2];     // prefetched x for current t (0 for inactive)
#pragma unroll
    for (int i = 0; i < NS2; ++i) {
        int idx = tid + i * NTH;
        int r = idx / E2W;
        int c = idx - r * E2W;
        int gy = ty0 + r - 2;
        int gx = tx0 + c - 2;
        bool ok = (idx < E2A) && ((unsigned)gy < HH) && ((unsigned)gx < WW);
        goff[i] = ok ? ((b * HH + gy) * WW + gx) : -1;
        v1[i] = 0.0f;
        xc[i] = 0.0f;
    }

    // ---- Phase-B: this thread owns a 2x2 block of E1 pixels ------------
    const bool active = (tid < NBLK);
    const int  br = tid / 17;            // block row (0..16)
    const int  bc = tid - br * 17;       // block col (0..16)
    const int  R  = 2 * br;              // E1 row of top-left pixel
    const int  C  = 2 * bc;              // E1 col of top-left pixel

    float    v2[4][4];                   // [pixel(dr*2+dc)][channel]
    unsigned ssum[4];                    // packed 4x8-bit channel counts
#pragma unroll
    for (int p = 0; p < 4; ++p) {
        ssum[p] = 0u;
#pragma unroll
        for (int ch = 0; ch < 4; ++ch) v2[p][ch] = 0.0f;
    }

    // ---- prefetch t = 0 -------------------------------------------------
#pragma unroll
    for (int i = 0; i < NS2; ++i)
        if (goff[i] >= 0) xc[i] = __ldg(x + goff[i]);

    __syncthreads();   // LUT ready

    // ====================== temporal loop ================================
    for (int t = 0; t < T_STEPS; ++t) {
        // Phase A: layer-1 LIF, ballot spikes into bit array
#pragma unroll
        for (int i = 0; i < NS2; ++i) {
            // v = v + (x-v)/2 : single-rounded, bit-identical to ref
            float v = fmaf(xc[i] - v1[i], 0.5f, v1[i]);
            bool sp = (v >= 1.0f);                // inactive lanes: never
            v1[i] = sp ? 0.0f : v;
            unsigned m = __ballot_sync(0xffffffffu, sp);
            if (lane == 0) BITS[wrp + i * NWARPS] = m;
        }
        // Prefetch next timestep's x (overlaps repack + Phase B)
        if (t + 1 < T_STEPS) {
            const float* xn = x + (size_t)(t + 1) * (BATCH * HH * WW);
#pragma unroll
            for (int i = 0; i < NS2; ++i)
                if (goff[i] >= 0) xc[i] = __ldg(xn + goff[i]);
        }
        __syncthreads();

        // Repack: per-row 36-bit masks (offset 4r mod 32 <= 28 -> 2 words)
        if (tid < E2W) {
            int bitoff = tid * E2W;
            int w  = bitoff >> 5;
            int sh = bitoff & 31;
            unsigned long long v =
                ((unsigned long long)BITS[w + 1] << 32) | BITS[w];
            ROW[tid] = v >> sh;
        }
        __syncthreads();

        // Phase B: patterns from row masks, LUT conv1, layer-2 LIF
        if (active) {
            unsigned long long r0 = ROW[R];
            unsigned long long r1 = ROW[R + 1];
            unsigned long long r2 = ROW[R + 2];
            unsigned long long r3 = ROW[R + 3];
            unsigned u0 = (unsigned)(r0 >> C) & 15u;
            unsigned u1 = (unsigned)(r1 >> C) & 15u;
            unsigned u2 = (unsigned)(r2 >> C) & 15u;
            unsigned u3 = (unsigned)(r3 >> C) & 15u;

            unsigned pat[4];
            pat[0] = (u0 & 7u) | ((u1 & 7u) << 3) | ((u2 & 7u) << 6);
            pat[1] = ((u0 >> 1) & 7u) | (((u1 >> 1) & 7u) << 3) | (((u2 >> 1) & 7u) << 6);
            pat[2] = (u1 & 7u) | ((u2 & 7u) << 3) | ((u3 & 7u) << 6);
            pat[3] = ((u1 >> 1) & 7u) | (((u2 >> 1) & 7u) << 3) | (((u3 >> 1) & 7u) << 6);

#pragma unroll
            for (int p = 0; p < 4; ++p) {
                float4 cc = LUT[pat[p]];
                unsigned add = 0u;
                float v;
                v = fmaf(cc.x - v2[p][0], 0.5f, v2[p][0]);
                if (v >= 1.0f) { add += 1u;       v = 0.0f; }
                v2[p][0] = v;
                v = fmaf(cc.y - v2[p][1], 0.5f, v2[p][1]);
                if (v >= 1.0f) { add += 1u << 8;  v = 0.0f; }
                v2[p][1] = v;
                v = fmaf(cc.z - v2[p][2], 0.5f, v2[p][2]);
                if (v >= 1.0f) { add += 1u << 16; v = 0.0f; }
                v2[p][2] = v;
                v = fmaf(cc.w - v2[p][3], 0.5f, v2[p][3]);
                if (v >= 1.0f) { add += 1u << 24; v = 0.0f; }
                v2[p][3] = v;
                ssum[p] += add;
            }
        }
        __syncthreads();   // protect BITS/ROW for next iteration
    }

    // ---- unpack spike counts into S2 planes (0 for out-of-image px) ----
    if (active) {
#pragma unroll
        for (int dr = 0; dr < 2; ++dr) {
#pragma unroll
            for (int dc = 0; dc < 2; ++dc) {
                int r = R + dr, c = C + dc;
                int gy = ty0 + r - 1;
                int gx = tx0 + c - 1;
                bool ok = ((unsigned)gy < HH) && ((unsigned)gx < WW);
                unsigned pk = ok ? ssum[dr * 2 + dc] : 0u;
                int idx = r * E1W + c;
                S2[idx]           = (float)( pk         & 255u);
                S2[E1A     + idx] = (float)((pk >> 8 )  & 255u);
                S2[2 * E1A + idx] = (float)((pk >> 16)  & 255u);
                S2[3 * E1A + idx] = (float)((pk >> 24)  & 255u);
            }
        }
    }
    __syncthreads();

    // ---- conv2 (3x3, 4->1ch) ONCE on summed spikes; divide by T --------
    // mean_t conv(s2_t, w2) = conv(sum_t s2_t, w2) / T   (linearity)
    float w2r[36];   // w2[0][c][ky][kx] -> w2r[c*9+ky*3+kx]
#pragma unroll
    for (int i = 0; i < 36; ++i) w2r[i] = __ldg(w2 + i);

    const float invT = 1.0f / (float)T_STEPS;
#pragma unroll
    for (int i = 0; i < 4; ++i) {
        int idx = tid + i * NTH;
        if (idx < TILE * TILE) {
            int r = idx >> 5;        // TILE = 32
            int c = idx & 31;
            int base = r * E1W + c;  // top-left tap of output (r,c)
            float acc = 0.0f;
#pragma unroll
            for (int ch = 0; ch < 4; ++ch) {
#pragma unroll
                for (int ky = 0; ky < 3; ++ky) {
#pragma unroll
                    for (int kx = 0; kx < 3; ++kx) {
                        acc = fmaf(S2[ch * E1A + base + ky * E1W + kx],
                                   w2r[ch * 9 + ky * 3 + kx], acc);
                    }
                }
            }
            out[(b * HH + ty0 + r) * WW + tx0 + c] = acc * invT;
        }
    }
}

extern "C" void kernel_launch(void* const* d_in, const int* in_sizes, int n_in,
                              void* d_out, int out_size)
{
    const float* x  = (const float*)d_in[0];
    const float* w1 = (const float*)d_in[1];
    const float* w2 = (const float*)d_in[2];
    float* out = (float*)d_out;

    dim3 grid(WW / TILE, HH / TILE, BATCH);   // (8, 8, 32)
    snn_kernel<<<grid, NTH>>>(x, w1, w2, out);
}

// round 5
// speedup vs baseline: 1.6101x; 1.6101x over previous
#include <cuda_runtime.h>

#define T_STEPS 16
#define BATCH   32
#define HH      256
#define WW      256
#define TILE    32
#define E2W     36              // tile + 2*2 halo (layer-1 extent)
#define E1W     34              // tile + 2*1 halo (layer-2 extent)
#define E2A     (E2W*E2W)       // 1296
#define E1A     (E1W*E1W)       // 1156
#define NTH     320             // 10 warps
#define NWARPS  (NTH/32)
#define NS2     5               // ceil(1296/320) phase-A slots
#define NBLK    289             // 17x17 2x2-pixel blocks covering E1
#define NBW     (NWARPS*NS2)    // 50 ballot words (linear bit array)

__global__ void __launch_bounds__(NTH, 2) snn_kernel(
    const float* __restrict__ x,
    const float* __restrict__ w1,
    const float* __restrict__ w2,
    float* __restrict__ out)
{
    __shared__ unsigned           BITS[NBW];             // spike bits, one t
    __shared__ unsigned           WANY[T_STEPS][NWARPS]; // per-t per-warp any
    __shared__ unsigned long long ROW[E2W];              // per-row bit masks
    __shared__ float4             LUT[512];              // conv1 per pattern
    __shared__ float              S2[4 * E1A];           // spike counts

    const int tid  = threadIdx.x;
    const int lane = tid & 31;
    const int wrp  = tid >> 5;
    const int tx0  = blockIdx.x * TILE;
    const int ty0  = blockIdx.y * TILE;
    const int b    = blockIdx.z;

    // ---- build conv1 LUT: bit (ky*3+kx) set => s1==1 at that tap --------
    {
        float w1r[36];
#pragma unroll
        for (int i = 0; i < 36; ++i) w1r[i] = __ldg(w1 + i);
        for (int p = tid; p < 512; p += NTH) {
            float a0 = 0.f, a1 = 0.f, a2 = 0.f, a3 = 0.f;
#pragma unroll
            for (int tap = 0; tap < 9; ++tap) {
                if (p & (1 << tap)) {
                    a0 += w1r[tap];
                    a1 += w1r[9  + tap];
                    a2 += w1r[18 + tap];
                    a3 += w1r[27 + tap];
                }
            }
            LUT[p] = make_float4(a0, a1, a2, a3);
        }
    }

    // ---- Phase-A slots: layer-1 state over E2 (tile + halo 2) ----------
    int   goff[NS2];   // offset into one time-slab of x, -1 if out of image
    float v1[NS2];
#pragma unroll
    for (int i = 0; i < NS2; ++i) {
        int idx = tid + i * NTH;
        int r = idx / E2W;
        int c = idx - r * E2W;
        int gy = ty0 + r - 2;
        int gx = tx0 + c - 2;
        bool ok = (idx < E2A) && ((unsigned)gy < HH) && ((unsigned)gx < WW);
        goff[i] = ok ? ((b * HH + gy) * WW + gx) : -1;
        v1[i] = 0.0f;
    }

    // ---- Phase-B: this thread owns a 2x2 block of E1 pixels ------------
    const bool active = (tid < NBLK);
    const int  br = tid / 17;            // block row (0..16)
    const int  bc = tid - br * 17;       // block col (0..16)
    const int  R  = 2 * br;              // E1 row of top-left pixel
    const int  C  = 2 * bc;              // E1 col of top-left pixel (<=32)

    float    v2[4][4];                   // [pixel(dr*2+dc)][channel]
    unsigned ssum[4];                    // packed 4x8-bit channel counts
#pragma unroll
    for (int p = 0; p < 4; ++p) {
        ssum[p] = 0u;
#pragma unroll
        for (int ch = 0; ch < 4; ++ch) v2[p][ch] = 0.0f;
    }

    // ---- depth-2 prefetch: t=0 -> xa, t=1 -> xb -------------------------
    const size_t SLAB = (size_t)BATCH * HH * WW;
    float xa[NS2], xb[NS2];
#pragma unroll
    for (int i = 0; i < NS2; ++i) { xa[i] = 0.0f; xb[i] = 0.0f; }
#pragma unroll
    for (int i = 0; i < NS2; ++i)
        if (goff[i] >= 0) {
            xa[i] = __ldg(x + goff[i]);
            xb[i] = __ldg(x + SLAB + goff[i]);
        }

    __syncthreads();   // LUT ready

    // one timestep; xc holds this step's x, then receives the t+2 prefetch
    auto step = [&](float (&xc)[NS2], int t) {
        // Phase A: layer-1 LIF, ballot spikes into linear bit array
        unsigned wany = 0u;
#pragma unroll
        for (int i = 0; i < NS2; ++i) {
            // v = v + (x-v)/2 : single-rounded, bit-identical to reference
            float v = fmaf(xc[i] - v1[i], 0.5f, v1[i]);
            bool sp = (v >= 1.0f);                 // inactive lanes: never
            v1[i] = sp ? 0.0f : v;
            unsigned m = __ballot_sync(0xffffffffu, sp);
            wany |= m;
            if (lane == 0) BITS[wrp + i * NWARPS] = m;
        }
        if (lane == 0) WANY[t][wrp] = wany;

        // Prefetch x for t+2 (consumed two iterations from now)
        if (t + 2 < T_STEPS) {
            const float* xn = x + (size_t)(t + 2) * SLAB;
#pragma unroll
            for (int i = 0; i < NS2; ++i)
                if (goff[i] >= 0) xc[i] = __ldg(xn + goff[i]);
        }
        __syncthreads();   // BITS/WANY[t] visible to all

        // Tile-level spike flag (CTA-uniform)
        unsigned f = (lane < NWARPS) ? WANY[t][lane] : 0u;
        unsigned flag = __reduce_or_sync(0xffffffffu, f);

        if (flag) {
            // --- spiking path (general-input correctness) ----------------
            if (tid < E2W) {   // repack: per-row 36-bit masks
                int bitoff = tid * E2W;
                int w  = bitoff >> 5;
                int sh = bitoff & 31;
                unsigned long long v =
                    ((unsigned long long)BITS[w + 1] << 32) | BITS[w];
                ROW[tid] = v >> sh;
            }
            __syncthreads();   // uniform branch: legal

            if (active) {
                const uint2* ROW32 = (const uint2*)ROW;
                uint2 r0 = ROW32[R];
                uint2 r1 = ROW32[R + 1];
                uint2 r2 = ROW32[R + 2];
                uint2 r3 = ROW32[R + 3];
                unsigned u0 = __funnelshift_rc(r0.x, r0.y, C) & 15u;
                unsigned u1 = __funnelshift_rc(r1.x, r1.y, C) & 15u;
                unsigned u2 = __funnelshift_rc(r2.x, r2.y, C) & 15u;
                unsigned u3 = __funnelshift_rc(r3.x, r3.y, C) & 15u;

                unsigned pat[4];
                pat[0] = (u0 & 7u) | ((u1 & 7u) << 3) | ((u2 & 7u) << 6);
                pat[1] = ((u0 >> 1) & 7u) | (((u1 >> 1) & 7u) << 3) | (((u2 >> 1) & 7u) << 6);
                pat[2] = (u1 & 7u) | ((u2 & 7u) << 3) | ((u3 & 7u) << 6);
                pat[3] = ((u1 >> 1) & 7u) | (((u2 >> 1) & 7u) << 3) | (((u3 >> 1) & 7u) << 6);

#pragma unroll
                for (int p = 0; p < 4; ++p) {
                    float4 cc = LUT[pat[p]];
                    unsigned add = 0u;
                    float v;
                    v = fmaf(cc.x - v2[p][0], 0.5f, v2[p][0]);
                    if (v >= 1.0f) { add += 1u;       v = 0.0f; }
                    v2[p][0] = v;
                    v = fmaf(cc.y - v2[p][1], 0.5f, v2[p][1]);
                    if (v >= 1.0f) { add += 1u << 8;  v = 0.0f; }
                    v2[p][1] = v;
                    v = fmaf(cc.z - v2[p][2], 0.5f, v2[p][2]);
                    if (v >= 1.0f) { add += 1u << 16; v = 0.0f; }
                    v2[p][2] = v;
                    v = fmaf(cc.w - v2[p][3], 0.5f, v2[p][3]);
                    if (v >= 1.0f) { add += 1u << 24; v = 0.0f; }
                    v2[p][3] = v;
                    ssum[p] += add;
                }
            }
            __syncthreads();   // BITS/ROW reads done before next overwrite
        } else {
            // --- empty-tile fast path: c1 == 0 exactly -------------------
            // v2' = v2/2, and LIF invariant (v2 < 1) gives v2/2 < V_TH:
            // no layer-2 spike possible; ssum unchanged. No barrier needed:
            // nobody read BITS, WANY slots are per-t, ROW untouched.
#pragma unroll
            for (int p = 0; p < 4; ++p) {
#pragma unroll
                for (int ch = 0; ch < 4; ++ch) v2[p][ch] *= 0.5f;
            }
        }
    };

    // ====================== temporal loop (unroll x2) ====================
#pragma unroll
    for (int t = 0; t < T_STEPS; t += 2) {
        step(xa, t);
        step(xb, t + 1);
    }

    // ---- unpack spike counts into S2 planes (0 for out-of-image px) ----
    if (active) {
#pragma unroll
        for (int dr = 0; dr < 2; ++dr) {
#pragma unroll
            for (int dc = 0; dc < 2; ++dc) {
                int r = R + dr, c = C + dc;
                int gy = ty0 + r - 1;
                int gx = tx0 + c - 1;
                bool ok = ((unsigned)gy < HH) && ((unsigned)gx < WW);
                unsigned pk = ok ? ssum[dr * 2 + dc] : 0u;
                int idx = r * E1W + c;
                S2[idx]           = (float)( pk         & 255u);
                S2[E1A     + idx] = (float)((pk >> 8 )  & 255u);
                S2[2 * E1A + idx] = (float)((pk >> 16)  & 255u);
                S2[3 * E1A + idx] = (float)((pk >> 24)  & 255u);
            }
        }
    }
    __syncthreads();

    // ---- conv2 (3x3, 4->1ch) ONCE on summed spikes; divide by T --------
    // mean_t conv(s2_t, w2) = conv(sum_t s2_t, w2) / T   (linearity)
    float w2r[36];   // w2[0][c][ky][kx] -> w2r[c*9+ky*3+kx]
#pragma unroll
    for (int i = 0; i < 36; ++i) w2r[i] = __ldg(w2 + i);

    const float invT = 1.0f / (float)T_STEPS;
#pragma unroll
    for (int i = 0; i < 4; ++i) {
        int idx = tid + i * NTH;
        if (idx < TILE * TILE) {
            int r = idx >> 5;        // TILE = 32
            int c = idx & 31;
            int base = r * E1W + c;  // top-left tap of output (r,c)
            float acc = 0.0f;
#pragma unroll
            for (int ch = 0; ch < 4; ++ch) {
#pragma unroll
                for (int ky = 0; ky < 3; ++ky) {
#pragma unroll
                    for (int kx = 0; kx < 3; ++kx) {
                        acc = fmaf(S2[ch * E1A + base + ky * E1W + kx],
                                   w2r[ch * 9 + ky * 3 + kx], acc);
                    }
                }
            }
            out[(b * HH + ty0 + r) * WW + tx0 + c] = acc * invT;
        }
    }
}

extern "C" void kernel_launch(void* const* d_in, const int* in_sizes, int n_in,
                              void* d_out, int out_size)
{
    const float* x  = (const float*)d_in[0];
    const float* w1 = (const float*)d_in[1];
    const float* w2 = (const float*)d_in[2];
    float* out = (float*)d_out;

    dim3 grid(WW / TILE, HH / TILE, BATCH);   // (8, 8, 32)
    snn_kernel<<<grid, NTH>>>(x, w1, w2, out);
}

// round 6
// speedup vs baseline: 3.4347x; 2.1332x over previous
#include <cuda_runtime.h>

#define T_STEPS 16
#define BATCH   32
#define HH      256
#define WW      256
#define NPIX    (BATCH*HH*WW)       // 2,097,152 pixels
#define TILE    32
#define E2W     36                  // tile + 2*2 halo (layer-1 spike extent)
#define E1W     34                  // tile + 2*1 halo (layer-2 extent)
#define E2A     (E2W*E2W)           // 1296
#define E1A     (E1W*E1W)           // 1156
#define NTH     320                 // K2: 10 warps
#define NWARPS  (NTH/32)
#define NS2     5                   // ceil(1296/320)
#define NBLK    289                 // 17x17 2x2-pixel blocks covering E1

// 4 MB spike scratch: bit t of g_spk[p] = layer-1 spike at pixel p, time t
__device__ unsigned short g_spk[NPIX];

// ========================= K1: pointwise LIF-1 ==========================
// One thread per pixel; 16 independent coalesced loads (MLP=16), recurrence
// in registers, one 2-byte store. No shared, no barriers, no halo.
__global__ void __launch_bounds__(256) lif1_kernel(const float* __restrict__ x)
{
    int p = blockIdx.x * 256 + threadIdx.x;
    float xv[T_STEPS];
#pragma unroll
    for (int t = 0; t < T_STEPS; ++t)
        xv[t] = __ldg(x + (size_t)t * NPIX + p);

    float v = 0.0f;
    unsigned bits = 0u;
#pragma unroll
    for (int t = 0; t < T_STEPS; ++t) {
        // v = v + (x-v)/2 : single-rounded, bit-identical to reference
        v = fmaf(xv[t] - v, 0.5f, v);
        if (v >= 1.0f) { bits |= 1u << t; v = 0.0f; }
    }
    g_spk[p] = (unsigned short)bits;
}

// ==================== K2: bit-domain LIF-2 + convs ======================
__global__ void __launch_bounds__(NTH, 2) lif2_kernel(
    const float* __restrict__ w1,
    const float* __restrict__ w2,
    float* __restrict__ out)
{
    __shared__ unsigned short     SW[E2A];            // spike words (16 t)
    __shared__ unsigned           WANY[NWARPS];
    __shared__ unsigned long long ROWS[T_STEPS][E2W]; // per-t row bit masks
    __shared__ float4             LUT[512];           // conv1 per 9-bit pat
    __shared__ float              S2[4 * E1A];        // channel spike counts

    const int tid  = threadIdx.x;
    const int lane = tid & 31;
    const int wrp  = tid >> 5;
    const int tx0  = blockIdx.x * TILE;
    const int ty0  = blockIdx.y * TILE;
    const int b    = blockIdx.z;

    // ---- load 36x36 spike words (halo-2, zero outside image) -----------
    unsigned myor = 0u;
#pragma unroll
    for (int i = 0; i < NS2; ++i) {
        int idx = tid + i * NTH;
        unsigned short w = 0;
        if (idx < E2A) {
            int r = idx / E2W;
            int c = idx - r * E2W;
            int gy = ty0 + r - 2;
            int gx = tx0 + c - 2;
            if (((unsigned)gy < HH) && ((unsigned)gx < WW))
                w = g_spk[(b * HH + gy) * WW + gx];
            SW[idx] = w;
        }
        myor |= w;
    }
    // tile-level 16-bit any-spike mask (uniform across CTA)
    unsigned wor = __reduce_or_sync(0xffffffffu, myor);
    if (lane == 0) WANY[wrp] = wor;
    __syncthreads();
    unsigned f = (lane < NWARPS) ? WANY[lane] : 0u;
    const unsigned tany = __reduce_or_sync(0xffffffffu, f);

    const int ob = (b * HH + ty0) * WW + tx0;   // output tile base

    if (tany == 0u) {
        // No layer-1 spikes at any timestep anywhere in this tile's halo:
        // c1 == 0 for all t => v2 decays from 0 => no layer-2 spikes =>
        // s2 counts are all zero => out = conv2(0)/T = 0 exactly.
#pragma unroll
        for (int i = 0; i < 4; ++i) {
            int idx = tid + i * NTH;
            if (idx < TILE * TILE)
                out[ob + (idx >> 5) * WW + (idx & 31)] = 0.0f;
        }
        return;
    }

    // =================== spiking path (general inputs) ==================
    // build conv1 LUT: bit (ky*3+kx) set => s1==1 at that tap
    {
        float w1r[36];
#pragma unroll
        for (int i = 0; i < 36; ++i) w1r[i] = __ldg(w1 + i);
        for (int p = tid; p < 512; p += NTH) {
            float a0 = 0.f, a1 = 0.f, a2 = 0.f, a3 = 0.f;
#pragma unroll
            for (int tap = 0; tap < 9; ++tap) {
                if (p & (1 << tap)) {
                    a0 += w1r[tap];
                    a1 += w1r[9  + tap];
                    a2 += w1r[18 + tap];
                    a3 += w1r[27 + tap];
                }
            }
            LUT[p] = make_float4(a0, a1, a2, a3);
        }
    }

    // repack: ROWS[t][r] = 36-bit spike row mask for timestep t
    for (int task = tid; task < T_STEPS * E2W; task += NTH) {
        int t = task / E2W;
        int r = task - t * E2W;
        if ((tany >> t) & 1u) {
            unsigned long long m = 0ull;
            const unsigned short* sr = SW + r * E2W;
#pragma unroll 4
            for (int c = 0; c < E2W; ++c)
                m |= (unsigned long long)((sr[c] >> t) & 1u) << c;
            ROWS[t][r] = m;
        }
    }
    __syncthreads();   // LUT + ROWS ready

    // this thread owns a 2x2 block of E1 pixels
    const bool active = (tid < NBLK);
    const int  br = tid / 17;
    const int  bc = tid - br * 17;
    const int  R  = 2 * br;              // E1 row of top-left pixel
    const int  C  = 2 * bc;              // E1 col of top-left pixel (<=32)

    float    v2[4][4];
    unsigned ssum[4];
#pragma unroll
    for (int p = 0; p < 4; ++p) {
        ssum[p] = 0u;
#pragma unroll
        for (int ch = 0; ch < 4; ++ch) v2[p][ch] = 0.0f;
    }

    // temporal loop: ROWS read-only => NO barriers inside
#pragma unroll 1
    for (int t = 0; t < T_STEPS; ++t) {
        if ((tany >> t) & 1u) {
            if (active) {
                const uint2* R32 = (const uint2*)ROWS[t];
                uint2 r0 = R32[R];
                uint2 r1 = R32[R + 1];
                uint2 r2 = R32[R + 2];
                uint2 r3 = R32[R + 3];
                unsigned u0 = __funnelshift_rc(r0.x, r0.y, C) & 15u;
                unsigned u1 = __funnelshift_rc(r1.x, r1.y, C) & 15u;
                unsigned u2 = __funnelshift_rc(r2.x, r2.y, C) & 15u;
                unsigned u3 = __funnelshift_rc(r3.x, r3.y, C) & 15u;

                unsigned pat[4];
                pat[0] = (u0 & 7u) | ((u1 & 7u) << 3) | ((u2 & 7u) << 6);
                pat[1] = ((u0 >> 1) & 7u) | (((u1 >> 1) & 7u) << 3) | (((u2 >> 1) & 7u) << 6);
                pat[2] = (u1 & 7u) | ((u2 & 7u) << 3) | ((u3 & 7u) << 6);
                pat[3] = ((u1 >> 1) & 7u) | (((u2 >> 1) & 7u) << 3) | (((u3 >> 1) & 7u) << 6);

#pragma unroll
                for (int p = 0; p < 4; ++p) {
                    float4 cc = LUT[pat[p]];
                    unsigned add = 0u;
                    float v;
                    v = fmaf(cc.x - v2[p][0], 0.5f, v2[p][0]);
                    if (v >= 1.0f) { add += 1u;       v = 0.0f; }
                    v2[p][0] = v;
                    v = fmaf(cc.y - v2[p][1], 0.5f, v2[p][1]);
                    if (v >= 1.0f) { add += 1u << 8;  v = 0.0f; }
                    v2[p][1] = v;
                    v = fmaf(cc.z - v2[p][2], 0.5f, v2[p][2]);
                    if (v >= 1.0f) { add += 1u << 16; v = 0.0f; }
                    v2[p][2] = v;
                    v = fmaf(cc.w - v2[p][3], 0.5f, v2[p][3]);
                    if (v >= 1.0f) { add += 1u << 24; v = 0.0f; }
                    v2[p][3] = v;
                    ssum[p] += add;
                }
            }
        } else {
            // empty step: c1 == 0 => v2' = v2/2; invariant v2 < 1 gives
            // v2/2 < V_TH: no spike possible, ssum unchanged.
#pragma unroll
            for (int p = 0; p < 4; ++p) {
#pragma unroll
                for (int ch = 0; ch < 4; ++ch) v2[p][ch] *= 0.5f;
            }
        }
    }
    __syncthreads();   // SW no longer needed; reuse shared region boundary

    // unpack spike counts into S2 planes (0 for out-of-image px)
    if (active) {
#pragma unroll
        for (int dr = 0; dr < 2; ++dr) {
#pragma unroll
            for (int dc = 0; dc < 2; ++dc) {
                int r = R + dr, c = C + dc;
                int gy = ty0 + r - 1;
                int gx = tx0 + c - 1;
                bool ok = ((unsigned)gy < HH) && ((unsigned)gx < WW);
                unsigned pk = ok ? ssum[dr * 2 + dc] : 0u;
                int idx = r * E1W + c;
                S2[idx]           = (float)( pk         & 255u);
                S2[E1A     + idx] = (float)((pk >> 8 )  & 255u);
                S2[2 * E1A + idx] = (float)((pk >> 16)  & 255u);
                S2[3 * E1A + idx] = (float)((pk >> 24)  & 255u);
            }
        }
    }
    __syncthreads();

    // conv2 (3x3, 4->1ch) ONCE on summed spikes; divide by T
    // mean_t conv(s2_t, w2) = conv(sum_t s2_t, w2) / T   (linearity)
    float w2r[36];
#pragma unroll
    for (int i = 0; i < 36; ++i) w2r[i] = __ldg(w2 + i);

    const float invT = 1.0f / (float)T_STEPS;
#pragma unroll
    for (int i = 0; i < 4; ++i) {
        int idx = tid + i * NTH;
        if (idx < TILE * TILE) {
            int r = idx >> 5;
            int c = idx & 31;
            int base = r * E1W + c;
            float acc = 0.0f;
#pragma unroll
            for (int ch = 0; ch < 4; ++ch) {
#pragma unroll
                for (int ky = 0; ky < 3; ++ky) {
#pragma unroll
                    for (int kx = 0; kx < 3; ++kx) {
                        acc = fmaf(S2[ch * E1A + base + ky * E1W + kx],
                                   w2r[ch * 9 + ky * 3 + kx], acc);
                    }
                }
            }
            out[ob + r * WW + c] = acc * invT;
        }
    }
}

extern "C" void kernel_launch(void* const* d_in, const int* in_sizes, int n_in,
                              void* d_out, int out_size)
{
    const float* x  = (const float*)d_in[0];
    const float* w1 = (const float*)d_in[1];
    const float* w2 = (const float*)d_in[2];
    float* out = (float*)d_out;

    lif1_kernel<<<NPIX / 256, 256>>>(x);

    dim3 grid(WW / TILE, HH / TILE, BATCH);   // (8, 8, 32)
    lif2_kernel<<<grid, NTH>>>(w1, w2, out);
}